// round 13
// baseline (speedup 1.0000x reference)
#include <cuda_runtime.h>
#include <stdint.h>

// Problem constants (fixed by the reference setup)
#define Bn 16
#define Pn 784
#define Dn 10000
#define Ln 1000
#define Cn 10

#define WSTRIDE 320    // padded words per row (320*32 = 10240 >= 10000)
#define NSS     5      // 5 superslabs of 64 words
#define NCH     7      // 7 pixel chunks of 112 (8 warps x 14)
#define NBP     8      // 8 batch pairs
#define NGROUP  (NBP * NSS)          // 40 (bp, ss) groups
#define NUNIT   (NGROUP * NCH)       // 280 compute units

// Per-sub-block shared memory (in 32-bit words):
//   sIdx2[112] | sBuf[4][2][7][32] uint2 (3584 w) | sEnc[2*64] | flags[2] | pad
#define SUB_WORDS  3840
#define SMEM_BYTES (4 * SUB_WORDS * 4)

// Scratch (allocation-free: device globals)
__device__ uint32_t g_vbits[Ln * WSTRIDE];     // sign bits of value_weight
__device__ uint32_t g_pbits[Pn * WSTRIDE];     // sign bits of position_weight
__device__ uint32_t g_idx2[NBP * Pn];          // packed level idx pair (lo|hi<<16)
__device__ uint2    g_chunk[NUNIT * 2 * 7 * 32]; // 7-plane chunk partials
__device__ float    g_partial[NSS * Bn * Cn];
__device__ int      g_gctr[NGROUP];            // per-group arrival counters
__device__ int      g_ctr2;                    // group completion counter
__device__ unsigned g_barctr;                  // grid-barrier arrivals
__device__ volatile unsigned g_gen;            // grid-barrier generation

// ---------------------------------------------------------------------------
__device__ __forceinline__ void fadd(uint32_t a, uint32_t b, uint32_t cin,
                                     uint32_t& s, uint32_t& cout)
{
    uint32_t t = a ^ b;
    s    = t ^ cin;
    cout = (a & b) | (cin & t);
}

// add (s weight1, c weight2) into 4-plane counter (capacity 15)
__device__ __forceinline__ void merge2(uint32_t s, uint32_t c, uint32_t* cp)
{
    uint32_t carry = cp[0] & s;
    cp[0] ^= s;
    uint32_t x, co;
    fadd(cp[1], c, carry, x, co);
    cp[1] = x;
    uint32_t nc = cp[2] ^ co; co &= cp[2]; cp[2] = nc;
    cp[3] ^= co;
}

// enc bit = 1 iff count < 392 (392 = 0b0110001000), 10 bit-planes
__device__ __forceinline__ uint32_t thr392(const uint32_t* c)
{
    uint32_t eq = ~0u, lt = 0u;
    eq &= ~c[9];
    lt |= eq & ~c[8]; eq &= c[8];
    lt |= eq & ~c[7]; eq &= c[7];
    eq &= ~c[6]; eq &= ~c[5]; eq &= ~c[4];
    lt |= eq & ~c[3];
    return lt;
}

#define BARS(id) asm volatile("bar.sync %0, 256;" :: "r"(id) : "memory")

// ---------------------------------------------------------------------------
// Phase 1: packed idx pairs + sign-bit packing of both bipolar tables.
// Permuted layout: word w, bit l <-> dim d = (w>>2)*128 + l*4 + (w&3).
// ---------------------------------------------------------------------------
__device__ void pack_phase(const float* __restrict__ x,
                           const float* __restrict__ posw,
                           const float* __restrict__ valw)
{
    const int tid     = blockIdx.x * blockDim.x + threadIdx.x;
    const int nthread = gridDim.x * blockDim.x;

    for (int i = tid; i < NBP * Pn; i += nthread) {
        int bp = i / Pn, p = i - bp * Pn;
        int qa = (int)rintf(x[(2 * bp)     * Pn + p] * 999.0f);
        int qb = (int)rintf(x[(2 * bp + 1) * Pn + p] * 999.0f);
        qa = min(max(qa, 0), Ln - 1);
        qb = min(max(qb, 0), Ln - 1);
        g_idx2[i] = (uint32_t)qa | ((uint32_t)qb << 16);
    }

    const int lane   = threadIdx.x & 31;
    const int warpId = tid >> 5;
    const int nWarps = nthread >> 5;
    const int totalTasks = (Ln + Pn) * 20;   // 20 x 512-dim tasks per row

    for (int task = warpId; task < totalTasks; task += nWarps) {
        int row = task / 20;
        int s   = task - row * 20;
        const float* src;
        uint32_t* dst;
        if (row < Ln) {
            src = valw + (size_t)row * Dn;
            dst = g_vbits + row * WSTRIDE;
        } else {
            src = posw + (size_t)(row - Ln) * Dn;
            dst = g_pbits + (row - Ln) * WSTRIDE;
        }

        uint32_t myword = 0;
        if (s < 19) {
            float4 v0 = *reinterpret_cast<const float4*>(src + s * 512 +   0 + lane * 4);
            float4 v1 = *reinterpret_cast<const float4*>(src + s * 512 + 128 + lane * 4);
            float4 v2 = *reinterpret_cast<const float4*>(src + s * 512 + 256 + lane * 4);
            float4 v3 = *reinterpret_cast<const float4*>(src + s * 512 + 384 + lane * 4);
#define PK(sub, vv)                                                          \
            {                                                                \
                uint32_t b0 = __ballot_sync(0xffffffffu, (vv).x < 0.0f);     \
                uint32_t b1 = __ballot_sync(0xffffffffu, (vv).y < 0.0f);     \
                uint32_t b2 = __ballot_sync(0xffffffffu, (vv).z < 0.0f);     \
                uint32_t b3 = __ballot_sync(0xffffffffu, (vv).w < 0.0f);     \
                if (lane == (sub)*4 + 0) myword = b0;                        \
                if (lane == (sub)*4 + 1) myword = b1;                        \
                if (lane == (sub)*4 + 2) myword = b2;                        \
                if (lane == (sub)*4 + 3) myword = b3;                        \
            }
            PK(0, v0) PK(1, v1) PK(2, v2) PK(3, v3)
#undef PK
        } else {
#pragma unroll
            for (int sub = 0; sub < 4; sub++) {
                int d0 = s * 512 + sub * 128 + lane * 4;
                bool valid = d0 < Dn;            // Dn % 4 == 0
                float4 v = make_float4(0.f, 0.f, 0.f, 0.f);
                if (valid) v = *reinterpret_cast<const float4*>(src + d0);
                uint32_t b0 = __ballot_sync(0xffffffffu, valid && v.x < 0.0f);
                uint32_t b1 = __ballot_sync(0xffffffffu, valid && v.y < 0.0f);
                uint32_t b2 = __ballot_sync(0xffffffffu, valid && v.z < 0.0f);
                uint32_t b3 = __ballot_sync(0xffffffffu, valid && v.w < 0.0f);
                if (lane == sub * 4 + 0) myword = b0;
                if (lane == sub * 4 + 1) myword = b1;
                if (lane == sub * 4 + 2) myword = b2;
                if (lane == sub * 4 + 3) myword = b3;
            }
        }
        if (lane < 16) dst[s * 16 + lane] = myword;      // coalesced 64B
    }
}

// ---------------------------------------------------------------------------
// Device-wide barrier. SAFE because grid == #SMs and the kernel is limited
// to 1 CTA/SM (1024 thr, <=64 regs, 60KB smem) -> all CTAs co-resident.
// Generation counter survives graph replays (output-deterministic).
// ---------------------------------------------------------------------------
__device__ __forceinline__ void grid_barrier()
{
    __syncthreads();
    if (threadIdx.x == 0) {
        unsigned myg = g_gen;
        __threadfence();                       // release phase-1 writes
        unsigned pos = atomicAdd(&g_barctr, 1u);
        if (pos == (unsigned)gridDim.x - 1u) {
            g_barctr = 0u;                     // self-reset for next replay
            __threadfence();
            atomicAdd((unsigned*)&g_gen, 1u);
        } else {
            while (g_gen == myg) { }           // HW-coherent volatile spin
        }
        __threadfence();                       // acquire
    }
    __syncthreads();
}

// ---------------------------------------------------------------------------
// Phase 2 unit: (bp, ss of 64 words, chunk of 112 pixels) on one 256-thread
// sub-block (8 warps x 14 pixels). Lane holds a word-pair (uint2, LDG.64);
// pbits loaded once per pixel and shared by both batches; 3:2 CSA into
// 4-plane counters (low regs); 3-round tree -> 7-plane chunk partial.
// 7th arriving unit of each (bp,ss) group: sum -> threshold -> enc ->
// coalesced classify; 40th group completion writes out.
// ---------------------------------------------------------------------------
__device__ void unit_phase(int u, uint32_t* __restrict__ S, int barid,
                           const float* __restrict__ cw, float* __restrict__ out)
{
    const int stid = threadIdx.x & 255;
    const int lane = stid & 31;
    const int wsub = stid >> 5;                  // 0..7
    const int bp   = u / (NSS * NCH);
    const int r0   = u - bp * (NSS * NCH);
    const int ss   = r0 / NCH;
    const int ch   = r0 - ss * NCH;
    const int grp  = bp * NSS + ss;

    uint32_t* __restrict__ sIdx2 = S;                       // 112
    uint2*    __restrict__ sBuf  = (uint2*)(S + 112);       // [4][2][7][32]
    uint32_t* __restrict__ sEnc  = S + 112 + 3584;          // [2][64]
    int*      __restrict__ sFlag = (int*)(S + 112 + 3584 + 128);

    if (stid < 112) sIdx2[stid] = g_idx2[bp * Pn + ch * 112 + stid];
    BARS(barid);

    const int wbase = ss * 64 + 2 * lane;        // first word of lane's pair
    const int p0    = ch * 112 + wsub * 14;      // global first pixel of warp

    uint32_t cnt[2][2][4];                       // [batch][comp][plane], <=14
#pragma unroll
    for (int b = 0; b < 2; b++)
#pragma unroll
        for (int c = 0; c < 2; c++)
#pragma unroll
            for (int j = 0; j < 4; j++) cnt[b][c][j] = 0u;

#pragma unroll
    for (int g = 0; g < 5; g++) {                // groups of 3,3,3,3,2 pixels
        const int gn = (g < 4) ? 3 : 2;
        const int pg = p0 + g * 3;
        const int lg = wsub * 14 + g * 3;
        uint32_t pr[3]; uint2 q[3], v[3];
#pragma unroll
        for (int k = 0; k < 3; k++) pr[k] = (k < gn) ? sIdx2[lg + k] : 0u;
#pragma unroll
        for (int k = 0; k < 3; k++)
            q[k] = (k < gn) ? __ldg(reinterpret_cast<const uint2*>(
                       g_pbits + (pg + k) * WSTRIDE + wbase))
                            : make_uint2(0u, 0u);
#pragma unroll
        for (int k = 0; k < 3; k++)              // pad: v=q -> XOR = 0
            v[k] = (k < gn) ? __ldg(reinterpret_cast<const uint2*>(
                       g_vbits + (pr[k] & 0xffffu) * WSTRIDE + wbase))
                            : q[k];
        {   // batch 0, both word components
            uint32_t t0 = v[0].x ^ q[0].x, t1 = v[1].x ^ q[1].x, t2 = v[2].x ^ q[2].x;
            merge2(t0 ^ t1 ^ t2, (t0 & t1) | (t2 & (t0 ^ t1)), cnt[0][0]);
            t0 = v[0].y ^ q[0].y; t1 = v[1].y ^ q[1].y; t2 = v[2].y ^ q[2].y;
            merge2(t0 ^ t1 ^ t2, (t0 & t1) | (t2 & (t0 ^ t1)), cnt[0][1]);
        }
#pragma unroll
        for (int k = 0; k < 3; k++)
            v[k] = (k < gn) ? __ldg(reinterpret_cast<const uint2*>(
                       g_vbits + (pr[k] >> 16) * WSTRIDE + wbase))
                            : q[k];
        {   // batch 1
            uint32_t t0 = v[0].x ^ q[0].x, t1 = v[1].x ^ q[1].x, t2 = v[2].x ^ q[2].x;
            merge2(t0 ^ t1 ^ t2, (t0 & t1) | (t2 & (t0 ^ t1)), cnt[1][0]);
            t0 = v[0].y ^ q[0].y; t1 = v[1].y ^ q[1].y; t2 = v[2].y ^ q[2].y;
            merge2(t0 ^ t1 ^ t2, (t0 & t1) | (t2 & (t0 ^ t1)), cnt[1][1]);
        }
    }

    // ---- 3-round tree reduction across 8 warps: 4 -> 7 planes ----
    uint32_t a[2][2][7];
#pragma unroll
    for (int b = 0; b < 2; b++)
#pragma unroll
        for (int c = 0; c < 2; c++) {
#pragma unroll
            for (int j = 0; j < 4; j++) a[b][c][j] = cnt[b][c][j];
            a[b][c][4] = a[b][c][5] = a[b][c][6] = 0u;
        }

#pragma unroll
    for (int r = 0; r < 3; r++) {
        const int half = 4 >> r;                 // 4,2,1 readers
        const int np   = 4 + r;                  // planes valid in sources
        if (wsub >= half && wsub < 2 * half) {
#pragma unroll
            for (int b = 0; b < 2; b++)
#pragma unroll
                for (int j = 0; j < 7; j++)
                    if (j < np)
                        sBuf[(((wsub - half) * 2 + b) * 7 + j) * 32 + lane] =
                            make_uint2(a[b][0][j], a[b][1][j]);
        }
        BARS(barid);
        if (wsub < half) {
#pragma unroll
            for (int b = 0; b < 2; b++) {
                uint32_t cx = 0u, cy = 0u;
#pragma unroll
                for (int j = 0; j < 7; j++) {
                    if (j < np) {
                        uint2 v = sBuf[((wsub * 2 + b) * 7 + j) * 32 + lane];
                        uint32_t s, co;
                        fadd(a[b][0][j], v.x, cx, s, co); a[b][0][j] = s; cx = co;
                        fadd(a[b][1][j], v.y, cy, s, co); a[b][1][j] = s; cy = co;
                    } else if (j == np) {
                        a[b][0][j] = cx; a[b][1][j] = cy;
                    }
                }
            }
        }
        BARS(barid);
    }

    if (wsub == 0) {                             // write 7-plane chunk partial
#pragma unroll
        for (int b = 0; b < 2; b++)
#pragma unroll
            for (int j = 0; j < 7; j++)
                g_chunk[((u * 2 + b) * 7 + j) * 32 + lane] =
                    make_uint2(a[b][0][j], a[b][1][j]);
    }
    BARS(barid);

    // ---- group arrival: 7th unit of this (bp,ss) runs phase B ----
    if (stid == 0) {
        __threadfence();
        int prev = atomicAdd(&g_gctr[grp], 1);
        sFlag[0] = (prev == NCH - 1);
        if (sFlag[0]) g_gctr[grp] = 0;           // reset for next replay
    }
    BARS(barid);
    if (!sFlag[0]) return;                       // whole sub exits uniformly

    __threadfence();                             // acquire peer chunk partials

    // ---- phase B: warps 0,1 (one per batch) sum 7 chunks -> enc ----
    if (wsub < 2) {
        uint32_t s[2][10];
#pragma unroll
        for (int c = 0; c < 2; c++)
#pragma unroll
            for (int j = 0; j < 10; j++) s[c][j] = 0u;
#pragma unroll
        for (int c2 = 0; c2 < NCH; c2++) {
            const int uc = grp * NCH + c2;       // unit id of chunk c2
            uint32_t cx = 0u, cy = 0u;
#pragma unroll
            for (int j = 0; j < 7; j++) {
                uint2 v = g_chunk[((uc * 2 + wsub) * 7 + j) * 32 + lane];
                uint32_t ss2, co;
                fadd(s[0][j], v.x, cx, ss2, co); s[0][j] = ss2; cx = co;
                fadd(s[1][j], v.y, cy, ss2, co); s[1][j] = ss2; cy = co;
            }
#pragma unroll
            for (int j = 7; j < 10; j++) {
                uint32_t nc = s[0][j] ^ cx; cx &= s[0][j]; s[0][j] = nc;
                nc = s[1][j] ^ cy; cy &= s[1][j]; s[1][j] = nc;
            }
        }
        sEnc[wsub * 64 + 2 * lane]     = thr392(s[0]);
        sEnc[wsub * 64 + 2 * lane + 1] = thr392(s[1]);
    }
    BARS(barid);

    // ---- coalesced classify: unit uu = b*10+c over dims [ss*2048, +2048) ----
    for (int uu = wsub; uu < 2 * Cn; uu += 8) {
        const int b = uu / Cn, c = uu - (uu / Cn) * Cn;
        const float* __restrict__ wrow = cw + c * Dn + ss * 2048;
        float acc = 0.0f;
#pragma unroll
        for (int i = 0; i < 16; i++) {
            int d0 = ss * 2048 + i * 128 + lane * 4;
            if (d0 < Dn) {                       // Dn%4==0 -> whole float4 valid
                uint32_t w0 = sEnc[b * 64 + i * 4 + 0];
                uint32_t w1 = sEnc[b * 64 + i * 4 + 1];
                uint32_t w2 = sEnc[b * 64 + i * 4 + 2];
                uint32_t w3 = sEnc[b * 64 + i * 4 + 3];
                float4 v = *reinterpret_cast<const float4*>(wrow + i * 128 + lane * 4);
                acc += ((w0 >> lane) & 1u) ? v.x : -v.x;
                acc += ((w1 >> lane) & 1u) ? v.y : -v.y;
                acc += ((w2 >> lane) & 1u) ? v.z : -v.z;
                acc += ((w3 >> lane) & 1u) ? v.w : -v.w;
            }
        }
#pragma unroll
        for (int off = 16; off >= 1; off >>= 1)  // deterministic fixed order
            acc += __shfl_xor_sync(0xffffffffu, acc, off);
        if (lane == 0) g_partial[(ss * Bn + (bp * 2 + b)) * Cn + c] = acc;
    }
    BARS(barid);

    // ---- 40th group completion writes the final output ----
    if (stid == 0) {
        __threadfence();
        int prev = atomicAdd(&g_ctr2, 1);
        sFlag[1] = (prev == NGROUP - 1);
    }
    BARS(barid);
    if (sFlag[1]) {
        __threadfence();
        if (stid < Bn * Cn) {
            float s = 0.0f;
#pragma unroll
            for (int sl = 0; sl < NSS; sl++) s += g_partial[sl * Bn * Cn + stid];
            out[stid] = s;
        }
        if (stid == 0) g_ctr2 = 0;               // reset for next replay
    }
}

// ---------------------------------------------------------------------------
__global__ void __launch_bounds__(1024, 1) hdc_fused_kernel(
    const float* __restrict__ x,    const float* __restrict__ posw,
    const float* __restrict__ valw, const float* __restrict__ cw,
    float* __restrict__ out)
{
    pack_phase(x, posw, valw);
    grid_barrier();

    extern __shared__ uint32_t smem[];
    const int sub = threadIdx.x >> 8;            // 0..3 sub-blocks of 256
    // bid-major mapping spreads units across all SMs
    for (int u = blockIdx.x + gridDim.x * sub; u < NUNIT; u += gridDim.x * 4) {
        unit_phase(u, smem + sub * SUB_WORDS, sub + 1, cw, out);
        break;                                   // each sub handles <=1 unit
    }
}

// ---------------------------------------------------------------------------
extern "C" void kernel_launch(void* const* d_in, const int* in_sizes, int n_in,
                              void* d_out, int out_size)
{
    const float* x    = (const float*)d_in[0];   // [16,28,28]
    const float* posw = (const float*)d_in[1];   // [784,10000]
    const float* valw = (const float*)d_in[2];   // [1000,10000]
    const float* cw   = (const float*)d_in[3];   // [10,10000]
    float* out = (float*)d_out;                  // [16,10]

    int dev = 0, smCount = 0;
    cudaGetDevice(&dev);
    cudaDeviceGetAttribute(&smCount, cudaDevAttrMultiProcessorCount, dev);
    if (smCount <= 0) smCount = 148;
    if (smCount * 4 < NUNIT) smCount = (NUNIT + 3) / 4;  // paranoia: keep <=1 unit/sub

    cudaFuncSetAttribute(hdc_fused_kernel,
                         cudaFuncAttributeMaxDynamicSharedMemorySize, SMEM_BYTES);
    hdc_fused_kernel<<<smCount, 1024, SMEM_BYTES>>>(x, posw, valw, cw, out);
}